// round 15
// baseline (speedup 1.0000x reference)
#include <cuda_runtime.h>
#include <cstdint>

#define NB 8
#define NT 4096
#define NC 1024      // C_in == C_out
#define NK 3
#define NWELEM (NK*NC*NC)   // 3145728
#define XSTRIDE (NT + 16)   // g_xq row stride in ints (8 guard ints each side)

// ---------------- device scratch (static; no allocations) ----------------
__device__ __align__(16) signed char g_wq[NK*NC*NC];     // [k][ic(32)][o][j(8 ints)]
__device__ __align__(16) int g_xq[NB*256*XSTRIDE];       // [(b*256+ig)][8 + t], guards zeroed
__device__ float g_mu[NB*NT];
__device__ float g_rstd[NB*NT];
__device__ unsigned int g_absmax[NB*NC];                 // float bits, >=0
__device__ double g_beta_acc;

// ---------------- fused init + sum |W| ----------------
__global__ void k_initwsum(const float* __restrict__ W) {
    int idx = blockIdx.x * blockDim.x + threadIdx.x;
    int gstride = gridDim.x * blockDim.x;
    for (int i = idx; i < NB*NC; i += gstride) g_absmax[i] = 0u;
    for (int i = idx; i < NB*256*16; i += gstride) {
        int row = i >> 4, g = i & 15;
        int col = (g < 8) ? g : (NT + g);
        g_xq[row * XSTRIDE + col] = 0;
    }
    if (idx == 0) g_beta_acc = 0.0;
    int tid = threadIdx.x;
    float s = 0.f;
    for (int i = idx; i < NWELEM; i += gstride)
        s += fabsf(W[i]);
    #pragma unroll
    for (int off = 16; off; off >>= 1) s += __shfl_xor_sync(0xFFFFFFFFu, s, off);
    __shared__ float rs[8];
    if ((tid & 31) == 0) rs[tid >> 5] = s;
    __syncthreads();
    if (tid == 0) {
        float tot = 0.f;
        #pragma unroll
        for (int w = 0; w < 8; w++) tot += rs[w];
        atomicAdd(&g_beta_acc, (double)tot);
    }
}

// ---------------- quantize weights: W[o][i][k] -> g_wq [k][ic][o][j] packed ----------------
__global__ void k_quantw(const float* __restrict__ W) {
    int idx = blockIdx.x * blockDim.x + threadIdx.x;
    int total = NK * NC * (NC/4);
    if (idx >= total) return;
    float beta = fmaxf((float)(g_beta_acc * (1.0 / (double)NWELEM)), 1e-5f);
    float inv_beta = 1.f / beta;
    int k  = idx / (NC * (NC/4));
    int r  = idx % (NC * (NC/4));
    int o  = r / (NC/4);
    int i4 = r % (NC/4);
    int p = 0;
    #pragma unroll
    for (int j = 0; j < 4; j++) {
        int i = i4*4 + j;
        float ws = W[(o*NC + i)*NK + k] * inv_beta;
        ws = fminf(fmaxf(ws, -1.f), 1.f);
        int q = (int)rintf(ws);
        p |= (q & 0xFF) << (8*j);
    }
    int ic = i4 >> 3, j8 = i4 & 7;
    ((int*)g_wq)[((k*32 + ic)*NC + o)*8 + j8] = p;
}

// ---------------- fused LN stats + channel abs-max: ONE DRAM pass via smem staging ----------------
#define STATS_SMEM (16*NC*4)   // 65536
__global__ void __launch_bounds__(256)
k_stats(const float* __restrict__ x,
        const float* __restrict__ gamma,
        const float* __restrict__ betaln) {
    extern __shared__ __align__(16) float sx[];   // [16][NC]
    __shared__ float s_mu[16], s_rs[16];
    __shared__ unsigned int s_max[NC];
    int tid = threadIdx.x;
    int lane = tid & 31, warp = tid >> 5;
    int b = blockIdx.y;
    int tbase = blockIdx.x * 32;

    #pragma unroll
    for (int h = 0; h < 4; h++) s_max[tid + h*256] = 0u;
    __syncthreads();

    #pragma unroll 1
    for (int half = 0; half < 2; half++) {
        int tb = tbase + half*16;
        const float4* xs = (const float4*)(x + ((size_t)(b*NT + tb)) * NC);
        float4* ss = (float4*)sx;
        #pragma unroll
        for (int i = 0; i < 16; i++)
            ss[tid + i*256] = xs[tid + i*256];
        __syncthreads();

        #pragma unroll
        for (int j = 0; j < 2; j++) {
            int rr = warp*2 + j;
            const float* xr = sx + rr*NC;
            float s = 0.f, s2 = 0.f;
            #pragma unroll 8
            for (int m = 0; m < 32; m++) {
                float v = xr[lane + 32*m];
                s += v; s2 += v*v;
            }
            #pragma unroll
            for (int off = 16; off; off >>= 1) {
                s  += __shfl_xor_sync(0xFFFFFFFFu, s,  off);
                s2 += __shfl_xor_sync(0xFFFFFFFFu, s2, off);
            }
            if (lane == 0) {
                float mu  = s * (1.f/NC);
                float var = fmaxf(s2 * (1.f/NC) - mu*mu, 0.f);
                float rstd = rsqrtf(var + 1e-5f);
                s_mu[rr] = mu; s_rs[rr] = rstd;
                g_mu[b*NT + tb + rr]   = mu;
                g_rstd[b*NT + tb + rr] = rstd;
            }
        }
        __syncthreads();

        #pragma unroll
        for (int h = 0; h < 4; h++) {
            int c = tid + h*256;
            float gm = gamma[c], bb = betaln[c];
            float mx = 0.f;
            #pragma unroll
            for (int rr = 0; rr < 16; rr++) {
                float v = fabsf((sx[rr*NC + c] - s_mu[rr]) * s_rs[rr] * gm + bb);
                mx = fmaxf(mx, v);
            }
            atomicMax(&s_max[c], __float_as_uint(mx));
        }
        __syncthreads();
    }

    #pragma unroll
    for (int h = 0; h < 4; h++) {
        int c = tid + h*256;
        atomicMax(&g_absmax[b*NC + c], s_max[c]);
    }
}

// ---------------- quantize + transpose x -> g_xq: float4-native, int-granular ----------------
__global__ void __launch_bounds__(256)
k_quantx(const float* __restrict__ x,
         const float* __restrict__ gamma,
         const float* __restrict__ betaln) {
    __shared__ int sq[32*65];
    int tid = threadIdx.x;
    int lane = tid & 31, warp = tid >> 5;
    int t0 = blockIdx.x * 64, c0 = blockIdx.y * 128, b = blockIdx.z;
    int cc = c0 + lane*4;

    float4 gm = *(const float4*)(gamma  + cc);
    float4 bt = *(const float4*)(betaln + cc);
    uint4  au = *(const uint4*)(g_absmax + b*NC + cc);
    float sc0 = 127.f / fmaxf(__uint_as_float(au.x), 1e-5f);
    float sc1 = 127.f / fmaxf(__uint_as_float(au.y), 1e-5f);
    float sc2 = 127.f / fmaxf(__uint_as_float(au.z), 1e-5f);
    float sc3 = 127.f / fmaxf(__uint_as_float(au.w), 1e-5f);

    #pragma unroll
    for (int it = 0; it < 8; it++) {
        int t = t0 + warp + 8*it;
        int row = b*NT + t;
        float mu = g_mu[row], rsd = g_rstd[row];
        float4 v = *(const float4*)(x + (size_t)row * NC + cc);
        float q0 = fminf(fmaxf(rintf(((v.x - mu)*rsd*gm.x + bt.x) * sc0), -127.f), 127.f);
        float q1 = fminf(fmaxf(rintf(((v.y - mu)*rsd*gm.y + bt.y) * sc1), -127.f), 127.f);
        float q2 = fminf(fmaxf(rintf(((v.z - mu)*rsd*gm.z + bt.z) * sc2), -127.f), 127.f);
        float q3 = fminf(fmaxf(rintf(((v.w - mu)*rsd*gm.w + bt.w) * sc3), -127.f), 127.f);
        int p = ((int)q0 & 0xFF) | (((int)q1 & 0xFF) << 8)
              | (((int)q2 & 0xFF) << 16) | (((int)q3 & 0xFF) << 24);
        sq[lane*65 + warp + 8*it] = p;
    }
    __syncthreads();

    int igbase = (c0 >> 2);
    #pragma unroll
    for (int rr = 0; rr < 4; rr++) {
        int ig = warp*4 + rr;
        #pragma unroll
        for (int h = 0; h < 2; h++) {
            int tt = h*32 + lane;
            g_xq[(size_t)(b*256 + igbase + ig) * XSTRIDE + 8 + t0 + tt] = sq[ig*65 + tt];
        }
    }
}

// ---------------- warp-specialized conv: producer/consumer mbarriers, no CTA barrier ----------------
// tile: 128 o x 128 t; warps 0-3 IMMA (cols 0..63), warps 4-7 dp4a (cols 64..127)
// 16 pipeline stages (2 chunks each); empty-mbar count=8 (one release-arrive per warp)

__device__ __forceinline__ void mma_s8(int& c0, int& c1, int& c2, int& c3,
                                       int a0, int a1, int a2, int a3,
                                       int b0, int b1) {
    asm volatile("mma.sync.aligned.m16n8k32.row.col.s32.s8.s8.s32 "
                 "{%0,%1,%2,%3}, {%4,%5,%6,%7}, {%8,%9}, {%0,%1,%2,%3};"
                 : "+r"(c0), "+r"(c1), "+r"(c2), "+r"(c3)
                 : "r"(a0), "r"(a1), "r"(a2), "r"(a3), "r"(b0), "r"(b1));
}
__device__ __forceinline__ void bulk_g2s(uint32_t dst, const void* src, uint32_t bytes, uint32_t mbar) {
    asm volatile("cp.async.bulk.shared::cta.global.mbarrier::complete_tx::bytes "
                 "[%0], [%1], %2, [%3];"
                 :: "r"(dst), "l"(src), "r"(bytes), "r"(mbar) : "memory");
}
__device__ __forceinline__ void mbar_init(uint32_t mbar, uint32_t count) {
    asm volatile("mbarrier.init.shared.b64 [%0], %1;" :: "r"(mbar), "r"(count) : "memory");
}
__device__ __forceinline__ void mbar_expect_tx(uint32_t mbar, uint32_t bytes) {
    asm volatile("mbarrier.arrive.expect_tx.shared.b64 _, [%0], %1;" :: "r"(mbar), "r"(bytes) : "memory");
}
__device__ __forceinline__ void mbar_arrive(uint32_t mbar) {
    asm volatile("mbarrier.arrive.shared.b64 _, [%0];" :: "r"(mbar) : "memory");
}
__device__ __forceinline__ void mbar_wait(uint32_t mbar, uint32_t parity) {
    asm volatile("{\n\t"
                 ".reg .pred P;\n\t"
                 "WL_%=:\n\t"
                 "mbarrier.try_wait.parity.acquire.cta.shared::cta.b64 P, [%0], %1, 0x989680;\n\t"
                 "@P bra WD_%=;\n\t"
                 "bra WL_%=;\n\t"
                 "WD_%=:\n\t"
                 "}" :: "r"(mbar), "r"(parity) : "memory");
}

#define BSTRIDE 152                  // ints per B smem row (152 % 32 == 24, conflict-free)
#define BROWB   560                  // bytes per B row copy (140 ints: t0-8 .. t0+131)
#define STAGE_TX (6*4096 + 16*BROWB) // 33536 bytes per 2-chunk stage
#define DPW 16                       // dp4a cols per lane group
#define SB_BASE 12288
#define CONV_SMEM (17152*4)          // 68608 bytes

__global__ void __launch_bounds__(256, 2)
k_conv_ws(float* __restrict__ out) {
    extern __shared__ __align__(16) int dsm[];
    __shared__ __align__(8) unsigned long long s_mbar[4];   // full0, full1, empty0, empty1

    int tid  = threadIdx.x;
    int lane = tid & 31, warp = tid >> 5;
    int t0 = blockIdx.x * 128;
    int o0 = blockIdx.y * 128;
    int b  = blockIdx.z;

    const char* wqb = (const char*)g_wq;
    const int*  xq  = g_xq;

    uint32_t dsm_u = (uint32_t)__cvta_generic_to_shared(dsm);
    uint32_t mbf[2], mbe[2];
    mbf[0] = (uint32_t)__cvta_generic_to_shared(&s_mbar[0]);
    mbf[1] = (uint32_t)__cvta_generic_to_shared(&s_mbar[1]);
    mbe[0] = (uint32_t)__cvta_generic_to_shared(&s_mbar[2]);
    mbe[1] = (uint32_t)__cvta_generic_to_shared(&s_mbar[3]);

    if (tid == 0) {
        mbar_init(mbf[0], 1); mbar_init(mbf[1], 1);
        mbar_init(mbe[0], 8); mbar_init(mbe[1], 8);   // one arrive per warp
    }
    __syncthreads();

    auto issue = [&](int st, int buf) {
        uint32_t mb = mbf[buf];
        uint32_t dA = dsm_u + buf*24576;
        uint32_t dB = dsm_u + SB_BASE*4 + buf*9728;
        mbar_expect_tx(mb, STAGE_TX);
        #pragma unroll
        for (int sc = 0; sc < 2; sc++)
            #pragma unroll
            for (int k = 0; k < 3; k++) {
                const void* src = wqb + ((size_t)((k*32 + st*2 + sc)*NC + o0) << 5);
                bulk_g2s(dA + sc*12288 + k*4096, src, 4096, mb);
            }
        #pragma unroll
        for (int ig2 = 0; ig2 < 16; ig2++) {
            const void* src = xq + (size_t)(b*256 + st*16 + ig2) * XSTRIDE + t0;
            bulk_g2s(dB + ig2*(BSTRIDE*4), src, BROWB, mb);
        }
    };

    int acc[64];
    #pragma unroll
    for (int i = 0; i < 64; i++) acc[i] = 0;

    int q = lane & 3, r = lane >> 2;
    int wm = warp & 3;
    int w2m = (warp - 4) & 3;
    int ubase = q*DPW;

    if (tid == 0) { issue(0, 0); issue(1, 1); }

    for (int st = 0; st < 16; st++) {
        int buf = st & 1;
        uint32_t par = (st >> 1) & 1;
        mbar_wait(mbf[buf], par);

        #pragma unroll 1
        for (int sc = 0; sc < 2; sc++) {
            const int* A = dsm + buf*6144 + sc*3072;
            const int* B = dsm + SB_BASE + buf*2432 + sc*(8*BSTRIDE);

            if (warp < 4) {
                #pragma unroll
                for (int k = 0; k < 3; k++) {
                    int a[2][4];
                    #pragma unroll
                    for (int mt = 0; mt < 2; mt++) {
                        int rb = wm*32 + mt*16;
                        const int* Ak = A + (k << 10);
                        a[mt][0] = Ak[((rb + r)     << 3) + q];
                        a[mt][1] = Ak[((rb + 8 + r) << 3) + q];
                        a[mt][2] = Ak[((rb + r)     << 3) + 4 + q];
                        a[mt][3] = Ak[((rb + 8 + r) << 3) + 4 + q];
                    }
                    #pragma unroll
                    for (int nt = 0; nt < 8; nt++) {
                        int col = nt*8 + r + k + 7;
                        int b0 = B[q*BSTRIDE + col];
                        int b1 = B[(4 + q)*BSTRIDE + col];
                        #pragma unroll
                        for (int mt = 0; mt < 2; mt++) {
                            int* ac = &acc[(mt*8 + nt)*4];
                            mma_s8(ac[0], ac[1], ac[2], ac[3],
                                   a[mt][0], a[mt][1], a[mt][2], a[mt][3], b0, b1);
                        }
                    }
                }
            } else {
                #pragma unroll 1
                for (int j = 0; j < 8; j++) {
                    int bb[24];
                    #pragma unroll
                    for (int i = 0; i < 6; i++) {
                        int4 v = *(const int4*)&B[j*BSTRIDE + 68 + ubase + 4*i];
                        bb[4*i+0] = v.x; bb[4*i+1] = v.y; bb[4*i+2] = v.z; bb[4*i+3] = v.w;
                    }
                    int a[3][4];
                    #pragma unroll
                    for (int k = 0; k < 3; k++)
                        #pragma unroll
                        for (int s = 0; s < 4; s++)
                            a[k][s] = A[((k*128 + w2m*32 + s*8 + r) << 3) + j];
                    #pragma unroll
                    for (int k = 0; k < 3; k++)
                        #pragma unroll
                        for (int s = 0; s < 4; s++)
                            #pragma unroll
                            for (int uu = 0; uu < DPW; uu++)
                                acc[s*DPW + uu] = __dp4a(a[k][s], bb[3 + uu + k], acc[s*DPW + uu]);
                }
            }
        }

        // release this buffer (one arrive per warp; arrive has release semantics)
        __syncwarp();
        if (lane == 0) mbar_arrive(mbe[buf]);

        // producer: refill this buffer for stage st+2 once all 8 warps released it
        if (tid == 0 && st + 2 < 16) {
            mbar_wait(mbe[buf], par);
            issue(st + 2, buf);
        }
    }

    // ---- epilogue ----
    float beta = fmaxf((float)(g_beta_acc * (1.0 / (double)NWELEM)), 1e-5f);
    if (warp < 4) {
        #pragma unroll
        for (int mt = 0; mt < 2; mt++) {
            int ro = o0 + wm*32 + mt*16 + r;
            float s0 = beta * fmaxf(__uint_as_float(g_absmax[b*NC + ro]),     1e-5f) * (1.f/127.f);
            float s1 = beta * fmaxf(__uint_as_float(g_absmax[b*NC + ro + 8]), 1e-5f) * (1.f/127.f);
            #pragma unroll
            for (int nt = 0; nt < 8; nt++) {
                int t = t0 + nt*8 + q*2;
                float* p0 = out + ((size_t)(b*NT + t)) * NC;
                float* p1 = p0 + NC;
                const int* ac = &acc[(mt*8 + nt)*4];
                p0[ro]     = (float)ac[0] * s0;
                p1[ro]     = (float)ac[1] * s0;
                p0[ro + 8] = (float)ac[2] * s1;
                p1[ro + 8] = (float)ac[3] * s1;
            }
        }
    } else {
        int tb = t0 + 64 + ubase;
        #pragma unroll
        for (int s = 0; s < 4; s++) {
            int ro = o0 + w2m*32 + s*8 + r;
            float osc = beta * fmaxf(__uint_as_float(g_absmax[b*NC + ro]), 1e-5f) * (1.f/127.f);
            #pragma unroll
            for (int uu = 0; uu < DPW; uu++) {
                int t = tb + uu;
                out[((size_t)(b*NT + t))*NC + ro] = (float)acc[s*DPW + uu] * osc;
            }
        }
    }
}

// ---------------- launch ----------------
extern "C" void kernel_launch(void* const* d_in, const int* in_sizes, int n_in,
                              void* d_out, int out_size) {
    const float* x      = (const float*)d_in[0];   // [8,4096,1024]
    const float* gamma  = (const float*)d_in[1];   // [1024]
    const float* betaln = (const float*)d_in[2];   // [1024]
    const float* W      = (const float*)d_in[3];   // [1024,1024,3]
    float* out = (float*)d_out;

    cudaFuncSetAttribute(k_conv_ws, cudaFuncAttributeMaxDynamicSharedMemorySize, CONV_SMEM);
    cudaFuncSetAttribute(k_stats,   cudaFuncAttributeMaxDynamicSharedMemorySize, STATS_SMEM);

    k_initwsum<<<1536, 256>>>(W);
    k_quantw<<<(NK*NC*(NC/4) + 255)/256, 256>>>(W);
    k_stats<<<dim3(NT/32, NB), 256, STATS_SMEM>>>(x, gamma, betaln);
    k_quantx<<<dim3(NT/64, NC/128, NB), 256>>>(x, gamma, betaln);
    k_conv_ws<<<dim3(NT/128, NC/128, NB), 256, CONV_SMEM>>>(out);
}

// round 16
// speedup vs baseline: 1.0073x; 1.0073x over previous
#include <cuda_runtime.h>
#include <cstdint>

#define NB 8
#define NT 4096
#define NC 1024      // C_in == C_out
#define NK 3
#define NWELEM (NK*NC*NC)   // 3145728
#define XSTRIDE (NT + 16)   // g_xq row stride in ints (8 guard ints each side)

// ---------------- device scratch (static; no allocations) ----------------
__device__ __align__(16) signed char g_wq[NK*NC*NC];     // [k][ic(32)][o][j(8 ints)]
__device__ __align__(16) int g_xq[NB*256*XSTRIDE];       // [(b*256+ig)][8 + t], guards zeroed
__device__ float g_mu[NB*NT];
__device__ float g_rstd[NB*NT];
__device__ unsigned int g_absmax[NB*NC];                 // float bits, >=0
__device__ double g_beta_acc;

// ---------------- fused init + sum |W| ----------------
__global__ void k_initwsum(const float* __restrict__ W) {
    int idx = blockIdx.x * blockDim.x + threadIdx.x;
    int gstride = gridDim.x * blockDim.x;
    for (int i = idx; i < NB*NC; i += gstride) g_absmax[i] = 0u;
    for (int i = idx; i < NB*256*16; i += gstride) {
        int row = i >> 4, g = i & 15;
        int col = (g < 8) ? g : (NT + g);
        g_xq[row * XSTRIDE + col] = 0;
    }
    if (idx == 0) g_beta_acc = 0.0;
    int tid = threadIdx.x;
    float s = 0.f;
    for (int i = idx; i < NWELEM; i += gstride)
        s += fabsf(W[i]);
    #pragma unroll
    for (int off = 16; off; off >>= 1) s += __shfl_xor_sync(0xFFFFFFFFu, s, off);
    __shared__ float rs[8];
    if ((tid & 31) == 0) rs[tid >> 5] = s;
    __syncthreads();
    if (tid == 0) {
        float tot = 0.f;
        #pragma unroll
        for (int w = 0; w < 8; w++) tot += rs[w];
        atomicAdd(&g_beta_acc, (double)tot);
    }
}

// ---------------- quantize weights: W[o][i][k] -> g_wq [k][ic][o][j] packed ----------------
__global__ void k_quantw(const float* __restrict__ W) {
    int idx = blockIdx.x * blockDim.x + threadIdx.x;
    int total = NK * NC * (NC/4);
    if (idx >= total) return;
    float beta = fmaxf((float)(g_beta_acc * (1.0 / (double)NWELEM)), 1e-5f);
    float inv_beta = 1.f / beta;
    int k  = idx / (NC * (NC/4));
    int r  = idx % (NC * (NC/4));
    int o  = r / (NC/4);
    int i4 = r % (NC/4);
    int p = 0;
    #pragma unroll
    for (int j = 0; j < 4; j++) {
        int i = i4*4 + j;
        float ws = W[(o*NC + i)*NK + k] * inv_beta;
        ws = fminf(fmaxf(ws, -1.f), 1.f);
        int q = (int)rintf(ws);
        p |= (q & 0xFF) << (8*j);
    }
    int ic = i4 >> 3, j8 = i4 & 7;
    ((int*)g_wq)[((k*32 + ic)*NC + o)*8 + j8] = p;
}

// ---------------- fused LN stats + channel abs-max: ONE DRAM pass via smem staging ----------------
#define STATS_SMEM (16*NC*4)   // 65536
__global__ void __launch_bounds__(256)
k_stats(const float* __restrict__ x,
        const float* __restrict__ gamma,
        const float* __restrict__ betaln) {
    extern __shared__ __align__(16) float sx[];   // [16][NC]
    __shared__ float s_mu[16], s_rs[16];
    __shared__ unsigned int s_max[NC];
    int tid = threadIdx.x;
    int lane = tid & 31, warp = tid >> 5;
    int b = blockIdx.y;
    int tbase = blockIdx.x * 32;

    #pragma unroll
    for (int h = 0; h < 4; h++) s_max[tid + h*256] = 0u;
    __syncthreads();

    #pragma unroll 1
    for (int half = 0; half < 2; half++) {
        int tb = tbase + half*16;
        const float4* xs = (const float4*)(x + ((size_t)(b*NT + tb)) * NC);
        float4* ss = (float4*)sx;
        #pragma unroll
        for (int i = 0; i < 16; i++)
            ss[tid + i*256] = xs[tid + i*256];
        __syncthreads();

        #pragma unroll
        for (int j = 0; j < 2; j++) {
            int rr = warp*2 + j;
            const float* xr = sx + rr*NC;
            float s = 0.f, s2 = 0.f;
            #pragma unroll 8
            for (int m = 0; m < 32; m++) {
                float v = xr[lane + 32*m];
                s += v; s2 += v*v;
            }
            #pragma unroll
            for (int off = 16; off; off >>= 1) {
                s  += __shfl_xor_sync(0xFFFFFFFFu, s,  off);
                s2 += __shfl_xor_sync(0xFFFFFFFFu, s2, off);
            }
            if (lane == 0) {
                float mu  = s * (1.f/NC);
                float var = fmaxf(s2 * (1.f/NC) - mu*mu, 0.f);
                float rstd = rsqrtf(var + 1e-5f);
                s_mu[rr] = mu; s_rs[rr] = rstd;
                g_mu[b*NT + tb + rr]   = mu;
                g_rstd[b*NT + tb + rr] = rstd;
            }
        }
        __syncthreads();

        #pragma unroll
        for (int h = 0; h < 4; h++) {
            int c = tid + h*256;
            float gm = gamma[c], bb = betaln[c];
            float mx = 0.f;
            #pragma unroll
            for (int rr = 0; rr < 16; rr++) {
                float v = fabsf((sx[rr*NC + c] - s_mu[rr]) * s_rs[rr] * gm + bb);
                mx = fmaxf(mx, v);
            }
            atomicMax(&s_max[c], __float_as_uint(mx));
        }
        __syncthreads();
    }

    #pragma unroll
    for (int h = 0; h < 4; h++) {
        int c = tid + h*256;
        atomicMax(&g_absmax[b*NC + c], s_max[c]);
    }
}

// ---------------- quantize + transpose x -> g_xq: float4-native, int-granular ----------------
__global__ void __launch_bounds__(256)
k_quantx(const float* __restrict__ x,
         const float* __restrict__ gamma,
         const float* __restrict__ betaln) {
    __shared__ int sq[32*65];
    int tid = threadIdx.x;
    int lane = tid & 31, warp = tid >> 5;
    int t0 = blockIdx.x * 64, c0 = blockIdx.y * 128, b = blockIdx.z;
    int cc = c0 + lane*4;

    float4 gm = *(const float4*)(gamma  + cc);
    float4 bt = *(const float4*)(betaln + cc);
    uint4  au = *(const uint4*)(g_absmax + b*NC + cc);
    float sc0 = 127.f / fmaxf(__uint_as_float(au.x), 1e-5f);
    float sc1 = 127.f / fmaxf(__uint_as_float(au.y), 1e-5f);
    float sc2 = 127.f / fmaxf(__uint_as_float(au.z), 1e-5f);
    float sc3 = 127.f / fmaxf(__uint_as_float(au.w), 1e-5f);

    #pragma unroll
    for (int it = 0; it < 8; it++) {
        int t = t0 + warp + 8*it;
        int row = b*NT + t;
        float mu = g_mu[row], rsd = g_rstd[row];
        float4 v = *(const float4*)(x + (size_t)row * NC + cc);
        float q0 = fminf(fmaxf(rintf(((v.x - mu)*rsd*gm.x + bt.x) * sc0), -127.f), 127.f);
        float q1 = fminf(fmaxf(rintf(((v.y - mu)*rsd*gm.y + bt.y) * sc1), -127.f), 127.f);
        float q2 = fminf(fmaxf(rintf(((v.z - mu)*rsd*gm.z + bt.z) * sc2), -127.f), 127.f);
        float q3 = fminf(fmaxf(rintf(((v.w - mu)*rsd*gm.w + bt.w) * sc3), -127.f), 127.f);
        int p = ((int)q0 & 0xFF) | (((int)q1 & 0xFF) << 8)
              | (((int)q2 & 0xFF) << 16) | (((int)q3 & 0xFF) << 24);
        sq[lane*65 + warp + 8*it] = p;
    }
    __syncthreads();

    int igbase = (c0 >> 2);
    #pragma unroll
    for (int rr = 0; rr < 4; rr++) {
        int ig = warp*4 + rr;
        #pragma unroll
        for (int h = 0; h < 2; h++) {
            int tt = h*32 + lane;
            g_xq[(size_t)(b*256 + igbase + ig) * XSTRIDE + 8 + t0 + tt] = sq[ig*65 + tt];
        }
    }
}

// ---------------- warp-specialized conv: 256-thread CTAs, 2/SM, 2-chunk stages ----------------
// (round-14 structure; producer copies split across 2 warps, each with own expect_tx)

__device__ __forceinline__ void mma_s8(int& c0, int& c1, int& c2, int& c3,
                                       int a0, int a1, int a2, int a3,
                                       int b0, int b1) {
    asm volatile("mma.sync.aligned.m16n8k32.row.col.s32.s8.s8.s32 "
                 "{%0,%1,%2,%3}, {%4,%5,%6,%7}, {%8,%9}, {%0,%1,%2,%3};"
                 : "+r"(c0), "+r"(c1), "+r"(c2), "+r"(c3)
                 : "r"(a0), "r"(a1), "r"(a2), "r"(a3), "r"(b0), "r"(b1));
}
__device__ __forceinline__ void bulk_g2s(uint32_t dst, const void* src, uint32_t bytes, uint32_t mbar) {
    asm volatile("cp.async.bulk.shared::cta.global.mbarrier::complete_tx::bytes "
                 "[%0], [%1], %2, [%3];"
                 :: "r"(dst), "l"(src), "r"(bytes), "r"(mbar) : "memory");
}
__device__ __forceinline__ void mbar_init(uint32_t mbar, uint32_t count) {
    asm volatile("mbarrier.init.shared.b64 [%0], %1;" :: "r"(mbar), "r"(count) : "memory");
}
__device__ __forceinline__ void mbar_expect_tx(uint32_t mbar, uint32_t bytes) {
    asm volatile("mbarrier.arrive.expect_tx.shared.b64 _, [%0], %1;" :: "r"(mbar), "r"(bytes) : "memory");
}
__device__ __forceinline__ void mbar_wait(uint32_t mbar, uint32_t parity) {
    asm volatile("{\n\t"
                 ".reg .pred P;\n\t"
                 "WL_%=:\n\t"
                 "mbarrier.try_wait.parity.acquire.cta.shared::cta.b64 P, [%0], %1, 0x989680;\n\t"
                 "@P bra WD_%=;\n\t"
                 "bra WL_%=;\n\t"
                 "WD_%=:\n\t"
                 "}" :: "r"(mbar), "r"(parity) : "memory");
}

#define BSTRIDE 152                  // ints per B smem row (152 % 32 == 24, conflict-free)
#define BROWB   560                  // bytes per B row copy (140 ints: t0-8 .. t0+131)
#define A_TX (6*4096)                // 24576 bytes of A per stage
#define B_TX (16*BROWB)              // 8960 bytes of B per stage
#define DPW 16                       // dp4a cols per lane group
#define SB_BASE 12288
#define CONV_SMEM (17152*4)          // 68608 bytes

__global__ void __launch_bounds__(256, 2)
k_conv_ws(float* __restrict__ out) {
    extern __shared__ __align__(16) int dsm[];
    __shared__ __align__(8) unsigned long long s_mbar[2];

    int tid  = threadIdx.x;
    int lane = tid & 31, warp = tid >> 5;
    int t0 = blockIdx.x * 128;
    int o0 = blockIdx.y * 128;
    int b  = blockIdx.z;

    const char* wqb = (const char*)g_wq;
    const int*  xq  = g_xq;

    uint32_t dsm_u = (uint32_t)__cvta_generic_to_shared(dsm);
    uint32_t mb0 = (uint32_t)__cvta_generic_to_shared(&s_mbar[0]);
    uint32_t mb1 = (uint32_t)__cvta_generic_to_shared(&s_mbar[1]);

    if (tid == 0) { mbar_init(mb0, 2); mbar_init(mb1, 2); }   // 2 expect_tx arrivals/stage
    __syncthreads();

    // producer split: tid 0 issues A copies (own expect_tx), tid 32 issues B copies (own expect_tx)
    auto issueA = [&](int st, int buf) {
        uint32_t mb = buf ? mb1 : mb0;
        uint32_t dA = dsm_u + buf*24576;
        mbar_expect_tx(mb, A_TX);
        #pragma unroll
        for (int sc = 0; sc < 2; sc++)
            #pragma unroll
            for (int k = 0; k < 3; k++) {
                const void* src = wqb + ((size_t)((k*32 + st*2 + sc)*NC + o0) << 5);
                bulk_g2s(dA + sc*12288 + k*4096, src, 4096, mb);
            }
    };
    auto issueB = [&](int st, int buf) {
        uint32_t mb = buf ? mb1 : mb0;
        uint32_t dB = dsm_u + SB_BASE*4 + buf*9728;
        mbar_expect_tx(mb, B_TX);
        #pragma unroll
        for (int ig2 = 0; ig2 < 16; ig2++) {
            const void* src = xq + (size_t)(b*256 + st*16 + ig2) * XSTRIDE + t0;
            bulk_g2s(dB + ig2*(BSTRIDE*4), src, BROWB, mb);
        }
    };

    int acc[64];
    #pragma unroll
    for (int i = 0; i < 64; i++) acc[i] = 0;

    int q = lane & 3, r = lane >> 2;
    int wm = warp & 3;
    int w2m = (warp - 4) & 3;
    int ubase = q*DPW;

    if (tid == 0)  issueA(0, 0);
    if (tid == 32) issueB(0, 0);

    for (int st = 0; st < 16; st++) {
        int buf = st & 1;
        if (st < 15 && tid == 0)  issueA(st + 1, buf ^ 1);
        if (st < 15 && tid == 32) issueB(st + 1, buf ^ 1);
        mbar_wait(buf ? mb1 : mb0, (st >> 1) & 1);

        #pragma unroll 1
        for (int sc = 0; sc < 2; sc++) {
            const int* A = dsm + buf*6144 + sc*3072;
            const int* B = dsm + SB_BASE + buf*2432 + sc*(8*BSTRIDE);

            if (warp < 4) {
                #pragma unroll
                for (int k = 0; k < 3; k++) {
                    int a[2][4];
                    #pragma unroll
                    for (int mt = 0; mt < 2; mt++) {
                        int rb = wm*32 + mt*16;
                        const int* Ak = A + (k << 10);
                        a[mt][0] = Ak[((rb + r)     << 3) + q];
                        a[mt][1] = Ak[((rb + 8 + r) << 3) + q];
                        a[mt][2] = Ak[((rb + r)     << 3) + 4 + q];
                        a[mt][3] = Ak[((rb + 8 + r) << 3) + 4 + q];
                    }
                    #pragma unroll
                    for (int nt = 0; nt < 8; nt++) {
                        int col = nt*8 + r + k + 7;
                        int b0 = B[q*BSTRIDE + col];
                        int b1 = B[(4 + q)*BSTRIDE + col];
                        #pragma unroll
                        for (int mt = 0; mt < 2; mt++) {
                            int* ac = &acc[(mt*8 + nt)*4];
                            mma_s8(ac[0], ac[1], ac[2], ac[3],
                                   a[mt][0], a[mt][1], a[mt][2], a[mt][3], b0, b1);
                        }
                    }
                }
            } else {
                #pragma unroll 1
                for (int j = 0; j < 8; j++) {
                    int bb[24];
                    #pragma unroll
                    for (int i = 0; i < 6; i++) {
                        int4 v = *(const int4*)&B[j*BSTRIDE + 68 + ubase + 4*i];
                        bb[4*i+0] = v.x; bb[4*i+1] = v.y; bb[4*i+2] = v.z; bb[4*i+3] = v.w;
                    }
                    int a[3][4];
                    #pragma unroll
                    for (int k = 0; k < 3; k++)
                        #pragma unroll
                        for (int s = 0; s < 4; s++)
                            a[k][s] = A[((k*128 + w2m*32 + s*8 + r) << 3) + j];
                    #pragma unroll
                    for (int k = 0; k < 3; k++)
                        #pragma unroll
                        for (int s = 0; s < 4; s++)
                            #pragma unroll
                            for (int uu = 0; uu < DPW; uu++)
                                acc[s*DPW + uu] = __dp4a(a[k][s], bb[3 + uu + k], acc[s*DPW + uu]);
                }
            }
        }
        __syncthreads();
    }

    // ---- epilogue ----
    float beta = fmaxf((float)(g_beta_acc * (1.0 / (double)NWELEM)), 1e-5f);
    if (warp < 4) {
        #pragma unroll
        for (int mt = 0; mt < 2; mt++) {
            int ro = o0 + wm*32 + mt*16 + r;
            float s0 = beta * fmaxf(__uint_as_float(g_absmax[b*NC + ro]),     1e-5f) * (1.f/127.f);
            float s1 = beta * fmaxf(__uint_as_float(g_absmax[b*NC + ro + 8]), 1e-5f) * (1.f/127.f);
            #pragma unroll
            for (int nt = 0; nt < 8; nt++) {
                int t = t0 + nt*8 + q*2;
                float* p0 = out + ((size_t)(b*NT + t)) * NC;
                float* p1 = p0 + NC;
                const int* ac = &acc[(mt*8 + nt)*4];
                p0[ro]     = (float)ac[0] * s0;
                p1[ro]     = (float)ac[1] * s0;
                p0[ro + 8] = (float)ac[2] * s1;
                p1[ro + 8] = (float)ac[3] * s1;
            }
        }
    } else {
        int tb = t0 + 64 + ubase;
        #pragma unroll
        for (int s = 0; s < 4; s++) {
            int ro = o0 + w2m*32 + s*8 + r;
            float osc = beta * fmaxf(__uint_as_float(g_absmax[b*NC + ro]), 1e-5f) * (1.f/127.f);
            #pragma unroll
            for (int uu = 0; uu < DPW; uu++) {
                int t = tb + uu;
                out[((size_t)(b*NT + t))*NC + ro] = (float)acc[s*DPW + uu] * osc;
            }
        }
    }
}

// ---------------- launch ----------------
extern "C" void kernel_launch(void* const* d_in, const int* in_sizes, int n_in,
                              void* d_out, int out_size) {
    const float* x      = (const float*)d_in[0];   // [8,4096,1024]
    const float* gamma  = (const float*)d_in[1];   // [1024]
    const float* betaln = (const float*)d_in[2];   // [1024]
    const float* W      = (const float*)d_in[3];   // [1024,1024,3]
    float* out = (float*)d_out;

    cudaFuncSetAttribute(k_conv_ws, cudaFuncAttributeMaxDynamicSharedMemorySize, CONV_SMEM);
    cudaFuncSetAttribute(k_stats,   cudaFuncAttributeMaxDynamicSharedMemorySize, STATS_SMEM);

    k_initwsum<<<1536, 256>>>(W);
    k_quantw<<<(NK*NC*(NC/4) + 255)/256, 256>>>(W);
    k_stats<<<dim3(NT/32, NB), 256, STATS_SMEM>>>(x, gamma, betaln);
    k_quantx<<<dim3(NT/64, NC/128, NB), 256>>>(x, gamma, betaln);
    k_conv_ws<<<dim3(NT/128, NC/128, NB), 256, CONV_SMEM>>>(out);
}